// round 3
// baseline (speedup 1.0000x reference)
#include <cuda_runtime.h>
#include <cuda_bf16.h>
#include <cstdint>

#define NPIX 262144               // 512*512 = 2^18
#define HALFCNT 4194304u          // half of total threefry count (4*8*NPIX/2)

// ---------------- device scratch (allocation-free) ----------------
__device__ float g_xt[4 * 210];
__device__ float g_acoef[4 * 8 * 2 * 6];  // [b][r][j][bb0,bb1,p,q,u,v]
__device__ float g_wr[4 * 8];             // softmaxed rank weights (first 8 of 9)
__device__ float g_scratch[32 * NPIX];    // w[b][r][n] plane-major (32 MiB)
__device__ unsigned int g_nrm[NPIX * 16]; // bf16 normals, interleaved [n][32] (16 MiB)
__device__ float g_part[4 * 256 * 44];    // gram partials per (b, block)
__device__ float g_Cc[4 * 8];             // combine coefs
__device__ float g_Ff[4 * 8];             // noise std coefs
__device__ float g_Kk[4];                 // mean shift

// ---------------- K0a: xt = x @ ctx_w^T + ctx_b ----------------
__global__ void k_xt(const float* __restrict__ x, const float* __restrict__ cw,
                     const float* __restrict__ cb) {
  int f = blockIdx.x;          // 0..209
  int t = threadIdx.x;         // 128 threads
  const float* wrow = cw + f * 512;
  float a0 = 0.f, a1 = 0.f, a2 = 0.f, a3 = 0.f;
  for (int i = t; i < 512; i += 128) {
    float w = wrow[i];
    a0 = fmaf(w, x[i], a0);
    a1 = fmaf(w, x[512 + i], a1);
    a2 = fmaf(w, x[1024 + i], a2);
    a3 = fmaf(w, x[1536 + i], a3);
  }
#pragma unroll
  for (int o = 16; o; o >>= 1) {
    a0 += __shfl_xor_sync(~0u, a0, o);
    a1 += __shfl_xor_sync(~0u, a1, o);
    a2 += __shfl_xor_sync(~0u, a2, o);
    a3 += __shfl_xor_sync(~0u, a3, o);
  }
  __shared__ float sm[4][4];
  int wq = t >> 5, l = t & 31;
  if (l == 0) { sm[wq][0] = a0; sm[wq][1] = a1; sm[wq][2] = a2; sm[wq][3] = a3; }
  __syncthreads();
  if (t == 0) {
    float bb = cb[f];
#pragma unroll
    for (int b = 0; b < 4; b++)
      g_xt[b * 210 + f] = sm[0][b] + sm[1][b] + sm[2][b] + sm[3][b] + bb;
  }
}

// ---------------- K0b: gate, affine modulation coefs, wr softmax ----------------
__global__ void k_mods() {
  int t = threadIdx.x;  // 128
  __shared__ float gated[4][105];
  for (int i = t; i < 420; i += 128) {
    int b = i / 105, k = i - 105 * b;
    float a1 = g_xt[b * 210 + k], a2 = g_xt[b * 210 + 105 + k];
    gated[b][k] = a1 * tanhf(a2);
  }
  __syncthreads();
  if (t < 64) {
    int b = t >> 4, r = (t >> 1) & 7, j = t & 1;
    int base = r * 12 + j * 2;
    float c0 = gated[b][base + 0] + 0.5f;
    float c1 = gated[b][base + 1];
    float bb0 = gated[b][base + 4];
    float bb1 = gated[b][base + 5];
    float s0 = gated[b][base + 8] + 1.0f;
    float s1 = gated[b][base + 9];
    float omc = 1.0f - c0;
    float p = s0 * omc + s1 * c1;
    float q = s0 * c1 - s1 * omc;
    float u = s0 * c0 - s1 * c1;
    float v = -(s0 * c1 + s1 * c0);
    float* dst = &g_acoef[((b * 8 + r) * 2 + j) * 6];
    dst[0] = bb0; dst[1] = bb1; dst[2] = p; dst[3] = q; dst[4] = u; dst[5] = v;
  }
  if (t < 4) {
    int b = t;
    float w[9];
#pragma unroll
    for (int i = 0; i < 9; i++) w[i] = gated[b][96 + i];
    w[8] += 0.35355339059327373f;  // 1/sqrt(8)
    float ss = 0.f;
#pragma unroll
    for (int i = 0; i < 9; i++) ss += w[i] * w[i];
    float inv = 1.0f / fmaxf(sqrtf(ss), 1e-12f);
    float mx = -3.4e38f;
#pragma unroll
    for (int i = 0; i < 9; i++) { w[i] *= inv; mx = fmaxf(mx, w[i]); }
    float sum = 0.f;
#pragma unroll
    for (int i = 0; i < 9; i++) { w[i] = expf(w[i] - mx); sum += w[i]; }
    float isum = 1.0f / sum;
#pragma unroll
    for (int i = 0; i < 8; i++) g_wr[b * 8 + i] = w[i] * isum;
  }
}

// ---------------- threefry2x32 (JAX, key = [0, 42]) ----------------
__device__ __forceinline__ void threefry(uint32_t c0, uint32_t c1,
                                         uint32_t& o0, uint32_t& o1) {
  const uint32_t K0 = 0u, K1 = 42u, K2 = 0x1BD11BDAu ^ 0u ^ 42u;
  uint32_t x0 = c0 + K0, x1 = c1 + K1;
#define TFR(rr) { x0 += x1; x1 = __funnelshift_l(x1, x1, rr); x1 ^= x0; }
  TFR(13) TFR(15) TFR(26) TFR(6)   x0 += K1; x1 += K2 + 1u;
  TFR(17) TFR(29) TFR(16) TFR(24)  x0 += K2; x1 += K0 + 2u;
  TFR(13) TFR(15) TFR(26) TFR(6)   x0 += K0; x1 += K1 + 3u;
  TFR(17) TFR(29) TFR(16) TFR(24)  x0 += K1; x1 += K2 + 4u;
  TFR(13) TFR(15) TFR(26) TFR(6)   x0 += K2; x1 += K0 + 5u;
#undef TFR
  o0 = x0; o1 = x1;
}

__device__ __forceinline__ float bits_to_normal(uint32_t bits) {
  float f = __uint_as_float((bits >> 9) | 0x3F800000u) - 1.0f;
  float x = fmaxf(-0.99999994f, fmaf(f, 2.0f, -0.99999994f));
  float w = -__logf(fmaf(x, -x, 1.0f));
  float p;
  if (w < 5.0f) {
    w -= 2.5f;
    p = 2.81022636e-08f;
    p = fmaf(p, w, 3.43273939e-07f);
    p = fmaf(p, w, -3.5233877e-06f);
    p = fmaf(p, w, -4.39150654e-06f);
    p = fmaf(p, w, 0.00021858087f);
    p = fmaf(p, w, -0.00125372503f);
    p = fmaf(p, w, -0.00417768164f);
    p = fmaf(p, w, 0.246640727f);
    p = fmaf(p, w, 1.50140941f);
  } else {
    w = sqrtf(w) - 3.0f;
    p = -0.000200214257f;
    p = fmaf(p, w, 0.000100950558f);
    p = fmaf(p, w, 0.00134934322f);
    p = fmaf(p, w, -0.00367342844f);
    p = fmaf(p, w, 0.00573950773f);
    p = fmaf(p, w, -0.0076224613f);
    p = fmaf(p, w, 0.00943887047f);
    p = fmaf(p, w, 1.00167406f);
    p = fmaf(p, w, 2.83297682f);
  }
  return 1.4142135623730951f * (p * x);
}

// ---------------- K1: fused w-pass (y=1..8) + noise generation (y=0) ----------------
__global__ void __launch_bounds__(256) k_wn(const float* __restrict__ wt) {
  int t = threadIdx.x;
  int n = blockIdx.x * 256 + t;
  if (blockIdx.y == 0) {
    // ---- noise blocks: 32 normals per pixel -> bf16 interleaved [n][32] ----
    float nm[32];
#pragma unroll
    for (int b2 = 0; b2 < 2; b2++) {
#pragma unroll
      for (int r = 0; r < 8; r++) {
        uint32_t j = (uint32_t)(b2 * 8 + r);
        uint32_t idx = (j << 18) | (uint32_t)n;
        uint32_t o0, o1;
        threefry(idx, idx + HALFCNT, o0, o1);
        nm[j] = bits_to_normal(o0);
        nm[j + 16] = bits_to_normal(o1);
      }
    }
    uint4 u[4];
    unsigned int* up = (unsigned int*)u;
#pragma unroll
    for (int k = 0; k < 16; k++) {
      __nv_bfloat162 h = __floats2bfloat162_rn(nm[2 * k], nm[2 * k + 1]);
      up[k] = *(unsigned int*)&h;
    }
    uint4* dst = (uint4*)&g_nrm[(size_t)n * 16];
#pragma unroll
    for (int k = 0; k < 4; k++) dst[k] = u[k];
  } else {
    // ---- w blocks: r = blockIdx.y - 1 ----
    int r = blockIdx.y - 1;
    __shared__ float scf[48];  // [b][j][6]
    if (t < 48) {
      int b = t / 12, rem = t % 12;
      scf[t] = g_acoef[((b * 8 + r) * 2 + (rem / 6)) * 6 + rem % 6];
    }
    __syncthreads();
    const float2* W = (const float2*)wt;
    float2 A0 = W[(size_t)(4 * r + 0) * NPIX + n];
    float2 A1 = W[(size_t)(4 * r + 1) * NPIX + n];
    float2 B0 = W[(size_t)(4 * r + 2) * NPIX + n];
    float2 B1 = W[(size_t)(4 * r + 3) * NPIX + n];
#pragma unroll
    for (int b = 0; b < 4; b++) {
      const float* c = &scf[b * 12];
      float nr = c[0] + c[2] * A0.x + c[3] * A0.y + c[4] * B0.x + c[5] * B0.y;
      float ni = c[1] - c[3] * A0.x + c[2] * A0.y - c[5] * B0.x + c[4] * B0.y;
      float er = c[6] + c[8] * A1.x + c[9] * A1.y + c[10] * B1.x + c[11] * B1.y;
      float ei = c[7] - c[9] * A1.x + c[8] * A1.y - c[11] * B1.x + c[10] * B1.y;
      float d2 = er * er + ei * ei;
      float inv = rsqrtf(fmaxf(d2, 1e-12f));
      float w = (nr * er + ni * ei) * inv;
      g_scratch[(size_t)(b * 8 + r) * NPIX + n] = w;
    }
  }
}

// triangular pair index: s <= t
#define TIDX(s, t) ((s) * 8 - (s) * ((s)-1) / 2 + ((t) - (s)))

// ---------------- K2: Gram + sums (float4, 1 elem per thread) ----------------
__global__ void __launch_bounds__(256) k_gram() {
  int b = blockIdx.y;
  int q = blockIdx.x * 256 + threadIdx.x;  // float4 index, < NPIX/4
  const float4* base = (const float4*)(g_scratch + (size_t)b * 8 * NPIX);
  float4 v[8];
#pragma unroll
  for (int s = 0; s < 8; s++) v[s] = base[(size_t)s * (NPIX / 4) + q];
  float a[36], su[8];
#pragma unroll
  for (int s = 0; s < 8; s++) su[s] = v[s].x + v[s].y + v[s].z + v[s].w;
#pragma unroll
  for (int s = 0; s < 8; s++)
#pragma unroll
    for (int u = s; u < 8; u++) {
      float acc = v[s].x * v[u].x;
      acc = fmaf(v[s].y, v[u].y, acc);
      acc = fmaf(v[s].z, v[u].z, acc);
      acc = fmaf(v[s].w, v[u].w, acc);
      a[TIDX(s, u)] = acc;
    }
#pragma unroll
  for (int k = 0; k < 36; k++)
#pragma unroll
    for (int o = 16; o; o >>= 1) a[k] += __shfl_xor_sync(~0u, a[k], o);
#pragma unroll
  for (int k = 0; k < 8; k++)
#pragma unroll
    for (int o = 16; o; o >>= 1) su[k] += __shfl_xor_sync(~0u, su[k], o);
  __shared__ float red[8][44];
  int wq = threadIdx.x >> 5;
  if ((threadIdx.x & 31) == 0) {
#pragma unroll
    for (int k = 0; k < 36; k++) red[wq][k] = a[k];
#pragma unroll
    for (int k = 0; k < 8; k++) red[wq][36 + k] = su[k];
  }
  __syncthreads();
  if (threadIdx.x < 44) {
    float acc = 0.f;
#pragma unroll
    for (int w2 = 0; w2 < 8; w2++) acc += red[w2][threadIdx.x];
    g_part[(b * 256 + blockIdx.x) * 44 + threadIdx.x] = acc;
  }
}

// ---------------- K3: finalize coefficients ----------------
__global__ void __launch_bounds__(704) k_fin() {
  __shared__ float ph[176][4];
  __shared__ float sG[176];
  int t = threadIdx.x;
  if (t < 704) {
    int pair = t >> 2, lane = t & 3;
    int b = pair / 44, j = pair % 44;
    float acc = 0.f;
    for (int blk = lane; blk < 256; blk += 4)
      acc += g_part[(b * 256 + blk) * 44 + j];
    ph[pair][lane] = acc;
  }
  __syncthreads();
  if (t < 176) sG[t] = ph[t][0] + ph[t][1] + ph[t][2] + ph[t][3];
  __syncthreads();
  if (t < 4) {
    int b = t;
    float G[8][8], S[8];
#pragma unroll
    for (int s = 0; s < 8; s++)
#pragma unroll
      for (int u = s; u < 8; u++) { float g = sG[b * 44 + TIDX(s, u)]; G[s][u] = g; G[u][s] = g; }
#pragma unroll
    for (int s = 0; s < 8; s++) S[s] = sG[b * 44 + 36 + s];
    float nc[8];
#pragma unroll
    for (int s = 0; s < 8; s++) nc[s] = fmaxf(sqrtf(G[s][s]), 1e-12f);
    float Gh[8][8];
#pragma unroll
    for (int s = 0; s < 8; s++)
#pragma unroll
      for (int u = 0; u < 8; u++) Gh[s][u] = G[s][u] / (nc[s] * nc[u]);
    const float alpha = 0.1f / (7.0f * 2.8284271247461903f);  // 0.1/(7*sqrt(8))
    float A[8][8];
#pragma unroll
    for (int s = 0; s < 8; s++)
#pragma unroll
      for (int u = 0; u < 8; u++) A[s][u] = (s == u) ? 1.0f : -alpha * Gh[s][u];
    float C[8], K = 0.f;
#pragma unroll
    for (int s = 0; s < 8; s++) C[s] = 0.f;
#pragma unroll
    for (int r = 0; r < 8; r++) {
      float q = 0.f;
#pragma unroll
      for (int u = 0; u < 8; u++) {
        float v = 0.f;
#pragma unroll
        for (int s = 0; s < 8; s++) v += A[r][s] * Gh[s][u];
        q += v * A[r][u];
      }
      float mc = fmaxf(sqrtf(fmaxf(q, 0.f)), 1e-12f);
      double meand = 0.0;
      float wr = g_wr[b * 8 + r];
#pragma unroll
      for (int s = 0; s < 8; s++) {
        float D = A[r][s] / (nc[s] * mc);
        C[s] += wr * D;
        meand += (double)D * (double)S[s];
      }
      meand /= (double)NPIX;
      double var = (1.0 - (double)NPIX * meand * meand) / (double)(NPIX - 1);
      if (var < 0.0) var = 0.0;
      double stdd = sqrt(var);
      if (stdd < 1e-12) stdd = 1e-12;
      g_Ff[b * 8 + r] = 0.01f * wr * (float)stdd;
      K += 0.01f * wr * (float)meand;
    }
#pragma unroll
    for (int s = 0; s < 8; s++) g_Cc[b * 8 + s] = C[s];
    g_Kk[b] = K;
  }
}

// ---------------- K4: combine + noise -> output (2 pixels/thread) ----------------
__global__ void __launch_bounds__(256) k_out(float* __restrict__ out) {
  __shared__ float sC[32], sF[32], sK[4];
  if (threadIdx.x < 32) { sC[threadIdx.x] = g_Cc[threadIdx.x]; sF[threadIdx.x] = g_Ff[threadIdx.x]; }
  if (threadIdx.x < 4) sK[threadIdx.x] = g_Kk[threadIdx.x];
  __syncthreads();
  int q = blockIdx.x * 256 + threadIdx.x;  // pixel-pair index, < NPIX/2
  const float2* S2 = (const float2*)g_scratch;
  float2 acc[4];
#pragma unroll
  for (int b = 0; b < 4; b++) { acc[b].x = sK[b]; acc[b].y = sK[b]; }
#pragma unroll
  for (int j = 0; j < 32; j++) {
    float2 v = S2[(size_t)j * (NPIX / 2) + q];
    float Cj = sC[j];
    int b = j >> 3;
    acc[b].x = fmaf(Cj, v.x, acc[b].x);
    acc[b].y = fmaf(Cj, v.y, acc[b].y);
  }
  const uint4* N4 = (const uint4*)g_nrm;
#pragma unroll
  for (int px = 0; px < 2; px++) {
    size_t n = (size_t)2 * q + px;
    float* ap = px ? &acc[0].y : &acc[0].x;  // strided access via component
#pragma unroll
    for (int k4 = 0; k4 < 4; k4++) {
      uint4 uu = N4[n * 4 + k4];
      unsigned int us[4] = {uu.x, uu.y, uu.z, uu.w};
#pragma unroll
      for (int c = 0; c < 4; c++) {
        int k = k4 * 4 + c;        // bf162 slot -> planes 2k, 2k+1
        __nv_bfloat162 h = *(__nv_bfloat162*)&us[c];
        float2 f = __bfloat1622float2(h);
        int jj = 2 * k;
        int b = jj >> 3;
        float a = px ? acc[b].y : acc[b].x;
        a = fmaf(sF[jj], f.x, a);
        a = fmaf(sF[jj + 1], f.y, a);
        if (px) acc[b].y = a; else acc[b].x = a;
      }
    }
    (void)ap;
  }
  float2* O2 = (float2*)out;
#pragma unroll
  for (int b = 0; b < 4; b++) O2[(size_t)b * (NPIX / 2) + q] = acc[b];
}

extern "C" void kernel_launch(void* const* d_in, const int* in_sizes, int n_in,
                              void* d_out, int out_size) {
  const float* x  = (const float*)d_in[0];
  const float* cw = (const float*)d_in[1];
  const float* cb = (const float*)d_in[2];
  const float* wt = (const float*)d_in[3];
  float* out = (float*)d_out;
  k_xt<<<210, 128>>>(x, cw, cb);
  k_mods<<<1, 128>>>();
  k_wn<<<dim3(NPIX / 256, 9), 256>>>(wt);
  k_gram<<<dim3(NPIX / 1024, 4), 256>>>();
  k_fin<<<1, 704>>>();
  k_out<<<NPIX / 512, 256>>>(out);
}

// round 4
// speedup vs baseline: 1.0251x; 1.0251x over previous
#include <cuda_runtime.h>
#include <cuda_bf16.h>
#include <cstdint>

#define NPIX 262144               // 512*512 = 2^18
#define HALFCNT 4194304u          // half of total threefry count (4*8*NPIX/2)
#define GBLK 128                  // k_gram blocks per batch
#define GITER 2                   // float4 iterations per gram thread

// ---------------- device scratch (allocation-free) ----------------
__device__ float g_xt[4 * 210];
__device__ float g_acoef[4 * 8 * 2 * 6];  // [b][r][j][bb0,bb1,p,q,u,v]
__device__ float g_wr[4 * 8];             // softmaxed rank weights (first 8 of 9)
__device__ float g_scratch[32 * NPIX];    // w[b][r][n] plane-major (32 MiB)
__device__ unsigned int g_nrm[NPIX * 16]; // bf16 normals, interleaved [n][32] (16 MiB)
__device__ float g_part[4 * GBLK * 44];   // gram partials per (b, block)
__device__ float g_Cc[4 * 8];             // combine coefs
__device__ float g_Ff[4 * 8];             // noise std coefs
__device__ float g_Kk[4];                 // mean shift

// ---------------- K0a: xt = x @ ctx_w^T + ctx_b ----------------
__global__ void k_xt(const float* __restrict__ x, const float* __restrict__ cw,
                     const float* __restrict__ cb) {
  int f = blockIdx.x;          // 0..209
  int t = threadIdx.x;         // 128 threads
  const float* wrow = cw + f * 512;
  float a0 = 0.f, a1 = 0.f, a2 = 0.f, a3 = 0.f;
  for (int i = t; i < 512; i += 128) {
    float w = wrow[i];
    a0 = fmaf(w, x[i], a0);
    a1 = fmaf(w, x[512 + i], a1);
    a2 = fmaf(w, x[1024 + i], a2);
    a3 = fmaf(w, x[1536 + i], a3);
  }
#pragma unroll
  for (int o = 16; o; o >>= 1) {
    a0 += __shfl_xor_sync(~0u, a0, o);
    a1 += __shfl_xor_sync(~0u, a1, o);
    a2 += __shfl_xor_sync(~0u, a2, o);
    a3 += __shfl_xor_sync(~0u, a3, o);
  }
  __shared__ float sm[4][4];
  int wq = t >> 5, l = t & 31;
  if (l == 0) { sm[wq][0] = a0; sm[wq][1] = a1; sm[wq][2] = a2; sm[wq][3] = a3; }
  __syncthreads();
  if (t == 0) {
    float bb = cb[f];
#pragma unroll
    for (int b = 0; b < 4; b++)
      g_xt[b * 210 + f] = sm[0][b] + sm[1][b] + sm[2][b] + sm[3][b] + bb;
  }
}

// ---------------- K0b: gate, affine modulation coefs, wr softmax ----------------
__global__ void k_mods() {
  int t = threadIdx.x;  // 128
  __shared__ float gated[4][105];
  for (int i = t; i < 420; i += 128) {
    int b = i / 105, k = i - 105 * b;
    float a1 = g_xt[b * 210 + k], a2 = g_xt[b * 210 + 105 + k];
    gated[b][k] = a1 * tanhf(a2);
  }
  __syncthreads();
  if (t < 64) {
    int b = t >> 4, r = (t >> 1) & 7, j = t & 1;
    int base = r * 12 + j * 2;
    float c0 = gated[b][base + 0] + 0.5f;
    float c1 = gated[b][base + 1];
    float bb0 = gated[b][base + 4];
    float bb1 = gated[b][base + 5];
    float s0 = gated[b][base + 8] + 1.0f;
    float s1 = gated[b][base + 9];
    float omc = 1.0f - c0;
    float p = s0 * omc + s1 * c1;
    float q = s0 * c1 - s1 * omc;
    float u = s0 * c0 - s1 * c1;
    float v = -(s0 * c1 + s1 * c0);
    float* dst = &g_acoef[((b * 8 + r) * 2 + j) * 6];
    dst[0] = bb0; dst[1] = bb1; dst[2] = p; dst[3] = q; dst[4] = u; dst[5] = v;
  }
  if (t < 4) {
    int b = t;
    float w[9];
#pragma unroll
    for (int i = 0; i < 9; i++) w[i] = gated[b][96 + i];
    w[8] += 0.35355339059327373f;  // 1/sqrt(8)
    float ss = 0.f;
#pragma unroll
    for (int i = 0; i < 9; i++) ss += w[i] * w[i];
    float inv = 1.0f / fmaxf(sqrtf(ss), 1e-12f);
    float mx = -3.4e38f;
#pragma unroll
    for (int i = 0; i < 9; i++) { w[i] *= inv; mx = fmaxf(mx, w[i]); }
    float sum = 0.f;
#pragma unroll
    for (int i = 0; i < 9; i++) { w[i] = expf(w[i] - mx); sum += w[i]; }
    float isum = 1.0f / sum;
#pragma unroll
    for (int i = 0; i < 8; i++) g_wr[b * 8 + i] = w[i] * isum;
  }
}

// ---------------- threefry2x32 (JAX, key = [0, 42]) ----------------
__device__ __forceinline__ void threefry(uint32_t c0, uint32_t c1,
                                         uint32_t& o0, uint32_t& o1) {
  const uint32_t K0 = 0u, K1 = 42u, K2 = 0x1BD11BDAu ^ 0u ^ 42u;
  uint32_t x0 = c0 + K0, x1 = c1 + K1;
#define TFR(rr) { x0 += x1; x1 = __funnelshift_l(x1, x1, rr); x1 ^= x0; }
  TFR(13) TFR(15) TFR(26) TFR(6)   x0 += K1; x1 += K2 + 1u;
  TFR(17) TFR(29) TFR(16) TFR(24)  x0 += K2; x1 += K0 + 2u;
  TFR(13) TFR(15) TFR(26) TFR(6)   x0 += K0; x1 += K1 + 3u;
  TFR(17) TFR(29) TFR(16) TFR(24)  x0 += K1; x1 += K2 + 4u;
  TFR(13) TFR(15) TFR(26) TFR(6)   x0 += K2; x1 += K0 + 5u;
#undef TFR
  o0 = x0; o1 = x1;
}

__device__ __forceinline__ float bits_to_normal(uint32_t bits) {
  float f = __uint_as_float((bits >> 9) | 0x3F800000u) - 1.0f;
  float x = fmaxf(-0.99999994f, fmaf(f, 2.0f, -0.99999994f));
  float w = -__logf(fmaf(x, -x, 1.0f));
  float p;
  if (w < 5.0f) {
    w -= 2.5f;
    p = 2.81022636e-08f;
    p = fmaf(p, w, 3.43273939e-07f);
    p = fmaf(p, w, -3.5233877e-06f);
    p = fmaf(p, w, -4.39150654e-06f);
    p = fmaf(p, w, 0.00021858087f);
    p = fmaf(p, w, -0.00125372503f);
    p = fmaf(p, w, -0.00417768164f);
    p = fmaf(p, w, 0.246640727f);
    p = fmaf(p, w, 1.50140941f);
  } else {
    w = sqrtf(w) - 3.0f;
    p = -0.000200214257f;
    p = fmaf(p, w, 0.000100950558f);
    p = fmaf(p, w, 0.00134934322f);
    p = fmaf(p, w, -0.00367342844f);
    p = fmaf(p, w, 0.00573950773f);
    p = fmaf(p, w, -0.0076224613f);
    p = fmaf(p, w, 0.00943887047f);
    p = fmaf(p, w, 1.00167406f);
    p = fmaf(p, w, 2.83297682f);
  }
  return 1.4142135623730951f * (p * x);
}

// ---------------- K1: role-interleaved w-pass + noise generation ----------------
// grid = 9216 1-D blocks; role = bid % 9 (0..7 = rank plane, 8 = noise).
// Consecutive 9 blocks cover all roles -> resident mix of mem-bound and
// ALU-bound blocks for pipe overlap.
__global__ void __launch_bounds__(256) k_wn(const float* __restrict__ wt) {
  int t = threadIdx.x;
  int bid = blockIdx.x;
  int role = bid % 9;
  int chunk = bid / 9;            // 0..1023
  int n = chunk * 256 + t;
  if (role == 8) {
    // ---- noise block: 32 normals per pixel -> bf16 interleaved [n][32] ----
    float nm[32];
#pragma unroll
    for (int b2 = 0; b2 < 2; b2++) {
#pragma unroll
      for (int r = 0; r < 8; r++) {
        uint32_t j = (uint32_t)(b2 * 8 + r);
        uint32_t idx = (j << 18) | (uint32_t)n;
        uint32_t o0, o1;
        threefry(idx, idx + HALFCNT, o0, o1);
        nm[j] = bits_to_normal(o0);
        nm[j + 16] = bits_to_normal(o1);
      }
    }
    uint4 u[4];
    unsigned int* up = (unsigned int*)u;
#pragma unroll
    for (int k = 0; k < 16; k++) {
      __nv_bfloat162 h = __floats2bfloat162_rn(nm[2 * k], nm[2 * k + 1]);
      up[k] = *(unsigned int*)&h;
    }
    uint4* dst = (uint4*)&g_nrm[(size_t)n * 16];
#pragma unroll
    for (int k = 0; k < 4; k++) dst[k] = u[k];
  } else {
    // ---- w block: rank plane r ----
    int r = role;
    __shared__ float scf[48];  // [b][j][6]
    if (t < 48) {
      int b = t / 12, rem = t % 12;
      scf[t] = g_acoef[((b * 8 + r) * 2 + (rem / 6)) * 6 + rem % 6];
    }
    __syncthreads();
    const float2* W = (const float2*)wt;
    float2 A0 = W[(size_t)(4 * r + 0) * NPIX + n];
    float2 A1 = W[(size_t)(4 * r + 1) * NPIX + n];
    float2 B0 = W[(size_t)(4 * r + 2) * NPIX + n];
    float2 B1 = W[(size_t)(4 * r + 3) * NPIX + n];
#pragma unroll
    for (int b = 0; b < 4; b++) {
      const float* c = &scf[b * 12];
      float nr = c[0] + c[2] * A0.x + c[3] * A0.y + c[4] * B0.x + c[5] * B0.y;
      float ni = c[1] - c[3] * A0.x + c[2] * A0.y - c[5] * B0.x + c[4] * B0.y;
      float er = c[6] + c[8] * A1.x + c[9] * A1.y + c[10] * B1.x + c[11] * B1.y;
      float ei = c[7] - c[9] * A1.x + c[8] * A1.y - c[11] * B1.x + c[10] * B1.y;
      float d2 = er * er + ei * ei;
      float inv = rsqrtf(fmaxf(d2, 1e-12f));
      float w = (nr * er + ni * ei) * inv;
      g_scratch[(size_t)(b * 8 + r) * NPIX + n] = w;
    }
  }
}

// triangular pair index: s <= t
#define TIDX(s, t) ((s) * 8 - (s) * ((s)-1) / 2 + ((t) - (s)))

// ---------------- K2: Gram + sums (float4, GITER elems per thread) ----------------
__global__ void __launch_bounds__(256) k_gram() {
  int b = blockIdx.y;
  const float4* base = (const float4*)(g_scratch + (size_t)b * 8 * NPIX);
  float a[36], su[8];
#pragma unroll
  for (int k = 0; k < 36; k++) a[k] = 0.f;
#pragma unroll
  for (int k = 0; k < 8; k++) su[k] = 0.f;
#pragma unroll
  for (int it = 0; it < GITER; it++) {
    int q = it * (GBLK * 256) + blockIdx.x * 256 + threadIdx.x;  // < NPIX/4
    float4 v[8];
#pragma unroll
    for (int s = 0; s < 8; s++) v[s] = base[(size_t)s * (NPIX / 4) + q];
#pragma unroll
    for (int s = 0; s < 8; s++) {
      su[s] += (v[s].x + v[s].y) + (v[s].z + v[s].w);
#pragma unroll
      for (int u = s; u < 8; u++) {
        float acc = a[TIDX(s, u)];
        acc = fmaf(v[s].x, v[u].x, acc);
        acc = fmaf(v[s].y, v[u].y, acc);
        acc = fmaf(v[s].z, v[u].z, acc);
        acc = fmaf(v[s].w, v[u].w, acc);
        a[TIDX(s, u)] = acc;
      }
    }
  }
#pragma unroll
  for (int k = 0; k < 36; k++)
#pragma unroll
    for (int o = 16; o; o >>= 1) a[k] += __shfl_xor_sync(~0u, a[k], o);
#pragma unroll
  for (int k = 0; k < 8; k++)
#pragma unroll
    for (int o = 16; o; o >>= 1) su[k] += __shfl_xor_sync(~0u, su[k], o);
  __shared__ float red[8][44];
  int wq = threadIdx.x >> 5;
  if ((threadIdx.x & 31) == 0) {
#pragma unroll
    for (int k = 0; k < 36; k++) red[wq][k] = a[k];
#pragma unroll
    for (int k = 0; k < 8; k++) red[wq][36 + k] = su[k];
  }
  __syncthreads();
  if (threadIdx.x < 44) {
    float acc = 0.f;
#pragma unroll
    for (int w2 = 0; w2 < 8; w2++) acc += red[w2][threadIdx.x];
    g_part[(b * GBLK + blockIdx.x) * 44 + threadIdx.x] = acc;
  }
}

// ---------------- K3: finalize coefficients ----------------
__global__ void __launch_bounds__(704) k_fin() {
  __shared__ float ph[176][4];
  __shared__ float sG[176];
  int t = threadIdx.x;
  if (t < 704) {
    int pair = t >> 2, lane = t & 3;
    int b = pair / 44, j = pair % 44;
    float acc = 0.f;
    for (int blk = lane; blk < GBLK; blk += 4)
      acc += g_part[(b * GBLK + blk) * 44 + j];
    ph[pair][lane] = acc;
  }
  __syncthreads();
  if (t < 176) sG[t] = ph[t][0] + ph[t][1] + ph[t][2] + ph[t][3];
  __syncthreads();
  if (t < 4) {
    int b = t;
    float G[8][8], S[8];
#pragma unroll
    for (int s = 0; s < 8; s++)
#pragma unroll
      for (int u = s; u < 8; u++) { float g = sG[b * 44 + TIDX(s, u)]; G[s][u] = g; G[u][s] = g; }
#pragma unroll
    for (int s = 0; s < 8; s++) S[s] = sG[b * 44 + 36 + s];
    float nc[8];
#pragma unroll
    for (int s = 0; s < 8; s++) nc[s] = fmaxf(sqrtf(G[s][s]), 1e-12f);
    float Gh[8][8];
#pragma unroll
    for (int s = 0; s < 8; s++)
#pragma unroll
      for (int u = 0; u < 8; u++) Gh[s][u] = G[s][u] / (nc[s] * nc[u]);
    const float alpha = 0.1f / (7.0f * 2.8284271247461903f);  // 0.1/(7*sqrt(8))
    float A[8][8];
#pragma unroll
    for (int s = 0; s < 8; s++)
#pragma unroll
      for (int u = 0; u < 8; u++) A[s][u] = (s == u) ? 1.0f : -alpha * Gh[s][u];
    float C[8], K = 0.f;
#pragma unroll
    for (int s = 0; s < 8; s++) C[s] = 0.f;
#pragma unroll
    for (int r = 0; r < 8; r++) {
      float q = 0.f;
#pragma unroll
      for (int u = 0; u < 8; u++) {
        float v = 0.f;
#pragma unroll
        for (int s = 0; s < 8; s++) v += A[r][s] * Gh[s][u];
        q += v * A[r][u];
      }
      float mc = fmaxf(sqrtf(fmaxf(q, 0.f)), 1e-12f);
      double meand = 0.0;
      float wr = g_wr[b * 8 + r];
#pragma unroll
      for (int s = 0; s < 8; s++) {
        float D = A[r][s] / (nc[s] * mc);
        C[s] += wr * D;
        meand += (double)D * (double)S[s];
      }
      meand /= (double)NPIX;
      double var = (1.0 - (double)NPIX * meand * meand) / (double)(NPIX - 1);
      if (var < 0.0) var = 0.0;
      double stdd = sqrt(var);
      if (stdd < 1e-12) stdd = 1e-12;
      g_Ff[b * 8 + r] = 0.01f * wr * (float)stdd;
      K += 0.01f * wr * (float)meand;
    }
#pragma unroll
    for (int s = 0; s < 8; s++) g_Cc[b * 8 + s] = C[s];
    g_Kk[b] = K;
  }
}

// ---------------- K4: combine + noise -> output (2 pixels/thread) ----------------
__global__ void __launch_bounds__(256) k_out(float* __restrict__ out) {
  __shared__ float sC[32], sF[32], sK[4];
  if (threadIdx.x < 32) { sC[threadIdx.x] = g_Cc[threadIdx.x]; sF[threadIdx.x] = g_Ff[threadIdx.x]; }
  if (threadIdx.x < 4) sK[threadIdx.x] = g_Kk[threadIdx.x];
  __syncthreads();
  int q = blockIdx.x * 256 + threadIdx.x;  // pixel-pair index, < NPIX/2
  const float2* S2 = (const float2*)g_scratch;
  float2 acc[4];
#pragma unroll
  for (int b = 0; b < 4; b++) { acc[b].x = sK[b]; acc[b].y = sK[b]; }
#pragma unroll
  for (int j = 0; j < 32; j++) {
    float2 v = S2[(size_t)j * (NPIX / 2) + q];
    float Cj = sC[j];
    int b = j >> 3;
    acc[b].x = fmaf(Cj, v.x, acc[b].x);
    acc[b].y = fmaf(Cj, v.y, acc[b].y);
  }
  const uint4* N4 = (const uint4*)g_nrm;
#pragma unroll
  for (int px = 0; px < 2; px++) {
    size_t n = (size_t)2 * q + px;
#pragma unroll
    for (int k4 = 0; k4 < 4; k4++) {
      uint4 uu = N4[n * 4 + k4];
      unsigned int us[4] = {uu.x, uu.y, uu.z, uu.w};
#pragma unroll
      for (int c = 0; c < 4; c++) {
        int k = k4 * 4 + c;        // bf162 slot -> planes 2k, 2k+1
        __nv_bfloat162 h = *(__nv_bfloat162*)&us[c];
        float2 f = __bfloat1622float2(h);
        int jj = 2 * k;
        int b = jj >> 3;
        float a = px ? acc[b].y : acc[b].x;
        a = fmaf(sF[jj], f.x, a);
        a = fmaf(sF[jj + 1], f.y, a);
        if (px) acc[b].y = a; else acc[b].x = a;
      }
    }
  }
  float2* O2 = (float2*)out;
#pragma unroll
  for (int b = 0; b < 4; b++) O2[(size_t)b * (NPIX / 2) + q] = acc[b];
}

extern "C" void kernel_launch(void* const* d_in, const int* in_sizes, int n_in,
                              void* d_out, int out_size) {
  const float* x  = (const float*)d_in[0];
  const float* cw = (const float*)d_in[1];
  const float* cb = (const float*)d_in[2];
  const float* wt = (const float*)d_in[3];
  float* out = (float*)d_out;
  k_xt<<<210, 128>>>(x, cw, cb);
  k_mods<<<1, 128>>>();
  k_wn<<<9 * (NPIX / 256), 256>>>(wt);
  k_gram<<<dim3(GBLK, 4), 256>>>();
  k_fin<<<1, 704>>>();
  k_out<<<NPIX / 512, 256>>>(out);
}